// round 15
// baseline (speedup 1.0000x reference)
#include <cuda_runtime.h>
#include <cuda_bf16.h>
#include <cstdint>

// ToroidalSOM squared-distance, single kernel, smem-free bf16 split-GEMM:
//   out[b, n] = ||x_b||^2 + ||w_n||^2 - 2 * dot(x_b, w_n)
// dot via mma.sync m16n8k16 bf16, 3 accumulated terms (hh + hl + lh) with
// A = -2*x (exact power-of-2 scale) so acc = -2*dot directly.
// Fragments are built per-lane straight from global memory (x is L1-resident,
// w streams once); no shared memory, no barriers, no ldmatrix, no prep kernel.
// Norms: per-lane fp32 partials over each lane's k-partition + quad shuffles.

#define DIM      64
#define NTOT     16384
#define BATCH    128
#define TILE_N   32
#define THREADS  128

typedef unsigned int u32;

#define MMA16816(c, a0v, a1v, a2v, a3v, b0v, b1v) \
    asm volatile("mma.sync.aligned.m16n8k16.row.col.f32.bf16.bf16.f32 " \
        "{%0,%1,%2,%3}, {%4,%5,%6,%7}, {%8,%9}, {%0,%1,%2,%3};" \
        : "+f"((c)[0]), "+f"((c)[1]), "+f"((c)[2]), "+f"((c)[3]) \
        : "r"(a0v), "r"(a1v), "r"(a2v), "r"(a3v), "r"(b0v), "r"(b1v))

// split (a, b) -> packed bf16x2 hi and bf16x2 lo (residual), low half = a
__device__ __forceinline__ void split2(float a, float b, u32& hi, u32& lo) {
    __nv_bfloat162 h = __floats2bfloat162_rn(a, b);
    hi = *(u32*)&h;
    float hf0 = __uint_as_float(hi << 16);
    float hf1 = __uint_as_float(hi & 0xFFFF0000u);
    __nv_bfloat162 l2 = __floats2bfloat162_rn(a - hf0, b - hf1);
    lo = *(u32*)&l2;
}

__global__ __launch_bounds__(THREADS)
void som_kernel(const float* __restrict__ x,
                const float* __restrict__ w,
                float* __restrict__ out)
{
    const int tid = threadIdx.x;
    const int wid = tid >> 5;
    const int l   = tid & 31;
    const int q   = l >> 2;          // 0..7
    const int t2  = (l & 3) * 2;     // 0,2,4,6
    const int m0  = wid * 32;        // warp's batch base (4 warps cover 128)
    const int nb  = blockIdx.x * TILE_N;

    // accumulators: acc[mt][nt][4] ; after MMA holds -2*dot
    float acc[2][4][4];
    #pragma unroll
    for (int mt = 0; mt < 2; mt++)
        #pragma unroll
        for (int nt = 0; nt < 4; nt++)
            #pragma unroll
            for (int r = 0; r < 4; r++) acc[mt][nt][r] = 0.f;

    // norm partials (fp32, exact)
    float xp[2][2] = {{0.f, 0.f}, {0.f, 0.f}};   // [mt][row: q / q+8]
    float wp[4]    = {0.f, 0.f, 0.f, 0.f};       // [nt] for col q

    // row base pointers
    const float* xr0 = x + (size_t)(m0 + q) * DIM;        // mt=0, row q
    const float* xr1 = xr0 + 8 * DIM;                     // mt=0, row q+8
    const float* xr2 = xr0 + 16 * DIM;                    // mt=1
    const float* xr3 = xr0 + 24 * DIM;
    const float* wr0 = w + (size_t)(nb + q) * DIM;        // nt=0, col q
    const float* wr1 = wr0 + 8 * DIM;
    const float* wr2 = wr0 + 16 * DIM;
    const float* wr3 = wr0 + 24 * DIM;

    #pragma unroll
    for (int ks = 0; ks < 4; ks++) {
        const int kk = ks * 16 + t2;

        // ---- A fragments: scaled s = -2*x, split hi/lo ----
        u32 ah[2][4], al[2][4];
        {
            const float* xra[2][2] = {{xr0, xr1}, {xr2, xr3}};
            #pragma unroll
            for (int mt = 0; mt < 2; mt++) {
                float2 v0 = *(const float2*)(xra[mt][0] + kk);      // (row,  k)
                float2 v1 = *(const float2*)(xra[mt][1] + kk);      // (row+8,k)
                float2 v2 = *(const float2*)(xra[mt][0] + kk + 8);  // (row,  k+8)
                float2 v3 = *(const float2*)(xra[mt][1] + kk + 8);  // (row+8,k+8)
                float2 s0 = make_float2(-2.f * v0.x, -2.f * v0.y);
                float2 s1 = make_float2(-2.f * v1.x, -2.f * v1.y);
                float2 s2 = make_float2(-2.f * v2.x, -2.f * v2.y);
                float2 s3 = make_float2(-2.f * v3.x, -2.f * v3.y);
                split2(s0.x, s0.y, ah[mt][0], al[mt][0]);
                split2(s1.x, s1.y, ah[mt][1], al[mt][1]);
                split2(s2.x, s2.y, ah[mt][2], al[mt][2]);
                split2(s3.x, s3.y, ah[mt][3], al[mt][3]);
                // norm partials: s*s = 4*x*x
                xp[mt][0] = fmaf(s0.x, s0.x, fmaf(s0.y, s0.y,
                             fmaf(s2.x, s2.x, fmaf(s2.y, s2.y, xp[mt][0]))));
                xp[mt][1] = fmaf(s1.x, s1.x, fmaf(s1.y, s1.y,
                             fmaf(s3.x, s3.x, fmaf(s3.y, s3.y, xp[mt][1]))));
            }
        }

        // ---- B fragments ----
        u32 bh[4][2], bl[4][2];
        {
            const float* wra[4] = {wr0, wr1, wr2, wr3};
            #pragma unroll
            for (int nt = 0; nt < 4; nt++) {
                float2 v0 = *(const float2*)(wra[nt] + kk);       // (k,   col)
                float2 v1 = *(const float2*)(wra[nt] + kk + 8);   // (k+8, col)
                split2(v0.x, v0.y, bh[nt][0], bl[nt][0]);
                split2(v1.x, v1.y, bh[nt][1], bl[nt][1]);
                wp[nt] = fmaf(v0.x, v0.x, fmaf(v0.y, v0.y,
                          fmaf(v1.x, v1.x, fmaf(v1.y, v1.y, wp[nt]))));
            }
        }

        // ---- 24 HMMA: hh, hl, lh ----
        #pragma unroll
        for (int mt = 0; mt < 2; mt++)
            #pragma unroll
            for (int nt = 0; nt < 4; nt++) {
                MMA16816(acc[mt][nt], ah[mt][0], ah[mt][1], ah[mt][2], ah[mt][3],
                         bh[nt][0], bh[nt][1]);
                MMA16816(acc[mt][nt], ah[mt][0], ah[mt][1], ah[mt][2], ah[mt][3],
                         bl[nt][0], bl[nt][1]);
                MMA16816(acc[mt][nt], al[mt][0], al[mt][1], al[mt][2], al[mt][3],
                         bh[nt][0], bh[nt][1]);
            }
    }

    // ---- reduce norms within quads (lanes sharing q, differing l&3) ----
    #pragma unroll
    for (int mt = 0; mt < 2; mt++)
        #pragma unroll
        for (int r = 0; r < 2; r++) {
            float v = xp[mt][r];
            v += __shfl_xor_sync(0xFFFFFFFFu, v, 1);
            v += __shfl_xor_sync(0xFFFFFFFFu, v, 2);
            xp[mt][r] = 0.25f * v;          // undo (-2)^2
        }
    #pragma unroll
    for (int nt = 0; nt < 4; nt++) {
        float v = wp[nt];
        v += __shfl_xor_sync(0xFFFFFFFFu, v, 1);
        v += __shfl_xor_sync(0xFFFFFFFFu, v, 2);
        wp[nt] = v;                          // wn for col (nb + nt*8 + q)
    }

    // redistribute wn: this lane's output cols are t2, t2+1 -> held at lanes
    // with q = t2 (srcLane = t2*4) and q = t2+1 (srcLane = t2*4 + 4)
    float wn0[4], wn1[4];
    #pragma unroll
    for (int nt = 0; nt < 4; nt++) {
        wn0[nt] = __shfl_sync(0xFFFFFFFFu, wp[nt], t2 * 4);
        wn1[nt] = __shfl_sync(0xFFFFFFFFu, wp[nt], t2 * 4 + 4);
    }

    // ---- epilogue: dist = acc(-2dot) + xn + wn; float2 stores ----
    #pragma unroll
    for (int mt = 0; mt < 2; mt++) {
        const int row0 = m0 + mt * 16 + q;
        const float xn0 = xp[mt][0];
        const float xn1 = xp[mt][1];
        #pragma unroll
        for (int nt = 0; nt < 4; nt++) {
            const size_t o = (size_t)row0 * NTOT + nb + nt * 8 + t2;
            float2 r0, r1;
            r0.x = acc[mt][nt][0] + (xn0 + wn0[nt]);
            r0.y = acc[mt][nt][1] + (xn0 + wn1[nt]);
            r1.x = acc[mt][nt][2] + (xn1 + wn0[nt]);
            r1.y = acc[mt][nt][3] + (xn1 + wn1[nt]);
            *(float2*)&out[o]                    = r0;
            *(float2*)&out[o + (size_t)8 * NTOT] = r1;
        }
    }
}

extern "C" void kernel_launch(void* const* d_in, const int* in_sizes, int n_in,
                              void* d_out, int out_size)
{
    const float* x = (const float*)d_in[0];   // (128, 64)
    const float* w = (const float*)d_in[1];   // (16384, 64)
    float* out = (float*)d_out;               // (128, 16384)

    som_kernel<<<NTOT / TILE_N, THREADS>>>(x, w, out);
}